// round 14
// baseline (speedup 1.0000x reference)
#include <cuda_runtime.h>
#include <cuda_bf16.h>

#define B_ 16
#define N_ 512
#define L_ 2048
#define DIM_ 768
#define M_ 8
#define CE_ 64
#define VOCAB_ 1024
#define H_ 128
#define G4H_ (4*H_)   // 512

// ---------------- scratch (device globals: no allocations allowed) ----------
__device__ float g_rep [B_*N_*M_*CE_];    // [B,N,512]  word char projections
__device__ float g_xcat[B_*L_*2*CE_];     // [B,L,128]  lstm input (char | padded)
__device__ float g_xpre[B_*L_*G4H_];      // [B,L,512]  x@W_ih^T + b_ih + b_hh
__device__ float g_hs  [B_*L_*H_];        // [B,L,128]  lstm hidden states
__device__ float g_WprojT[G4H_*DIM_];     // [512,768]  W_proj transposed (N,K)
__device__ float g_WpredT[VOCAB_*H_];     // [1024,128] W_pred transposed (N,K)
__device__ float g_bias2[G4H_];           // b_ih + b_hh
__device__ int   g_woff[B_*N_];           // exclusive prefix sum of word lens

// ---------------- f32x2 / misc helpers ---------------------------------------
static __device__ __forceinline__ unsigned long long pack2(float lo, float hi) {
    unsigned long long r;
    asm("mov.b64 %0, {%1, %2};" : "=l"(r) : "f"(lo), "f"(hi));
    return r;
}
static __device__ __forceinline__ float2 unpack2(unsigned long long v) {
    float2 r;
    asm("mov.b64 {%0, %1}, %2;" : "=f"(r.x), "=f"(r.y) : "l"(v));
    return r;
}
static __device__ __forceinline__ unsigned long long ffma2(
    unsigned long long a, unsigned long long b, unsigned long long c) {
    unsigned long long d;
    asm("fma.rn.f32x2 %0, %1, %2, %3;" : "=l"(d) : "l"(a), "l"(b), "l"(c));
    return d;
}
static __device__ __forceinline__ float fast_tanh(float x) {
    float r;
    asm("tanh.approx.f32 %0, %1;" : "=f"(r) : "f"(x));
    return r;
}
static __device__ __forceinline__ float fast_sigmoid(float x) {
    float r;
    asm("tanh.approx.f32 %0, %1;" : "=f"(r) : "f"(0.5f * x));
    return fmaf(0.5f, r, 0.5f);
}
static __device__ __forceinline__ unsigned tf32_of(float f) {
    unsigned u;
    asm("cvt.rna.tf32.f32 %0, %1;" : "=r"(u) : "f"(f));
    return u;
}
static __device__ __forceinline__ unsigned smem_u32(const void* p) {
    return (unsigned)__cvta_generic_to_shared(p);
}

// ---------------- prep: combine biases ---------------------------------------
__global__ void prep_bias_kernel(const float* __restrict__ b_ih,
                                 const float* __restrict__ b_hh) {
    int i = blockIdx.x * blockDim.x + threadIdx.x;
    if (i < G4H_) g_bias2[i] = b_ih[i] + b_hh[i];
}

// ---------------- tiled transpose: dst[C][R] = src[R][C] ---------------------
__global__ void transpose_kernel(const float* __restrict__ src,
                                 float* __restrict__ dst, int R, int C) {
    __shared__ float t[32][33];
    int bx = blockIdx.x * 32, by = blockIdx.y * 32;
    int x = bx + threadIdx.x;
    #pragma unroll
    for (int dy = 0; dy < 32; dy += 8)
        t[threadIdx.y + dy][threadIdx.x] = src[(long)(by + threadIdx.y + dy) * C + x];
    __syncthreads();
    int x2 = by + threadIdx.x;
    #pragma unroll
    for (int dy = 0; dy < 32; dy += 8)
        dst[(long)(bx + threadIdx.y + dy) * R + x2] = t[threadIdx.x][threadIdx.y + dy];
}

// ---------------- per-batch exclusive prefix sum of word lens ---------------
__global__ void scan_lens_kernel(const int* __restrict__ lens) {
    __shared__ int s[N_];
    int b = blockIdx.x, tid = threadIdx.x;
    int v0 = lens[b * N_ + tid];
    s[tid] = v0;
    __syncthreads();
    #pragma unroll
    for (int off = 1; off < N_; off <<= 1) {
        int v = (tid >= off) ? s[tid - off] : 0;
        __syncthreads();
        s[tid] += v;
        __syncthreads();
    }
    g_woff[b * N_ + tid] = s[tid] - v0;   // exclusive
}

// ---------------- build x_cat: char embedding + zero padded half ------------
__global__ void build_char_kernel(const int* __restrict__ ids,
                                  const float* __restrict__ emb) {
    long i = (long)blockIdx.x * blockDim.x + threadIdx.x;   // one float4 each
    if (i >= (long)B_ * L_ * 32) return;
    int q = (int)(i & 31);
    long bt = i >> 5;
    float4* dst = (float4*)(g_xcat + bt * 128);
    if (q < 16) {
        int id = ids[bt];
        dst[q] = ((const float4*)(emb + (long)id * CE_))[q];
    } else {
        dst[q] = make_float4(0.f, 0.f, 0.f, 0.f);
    }
}

// ---------------- ragged scatter of word char projections -------------------
__global__ void scatter_pad_kernel(const int* __restrict__ lens) {
    int w = (blockIdx.x * blockDim.x + threadIdx.x) >> 5;   // one warp per word
    int lane = threadIdx.x & 31;
    if (w >= B_ * N_) return;
    int b = w / N_;
    int len = lens[w];
    int off = g_woff[w];
    for (int m = 0; m < len; m++) {
        int pos = off + m;
        if (pos >= L_) break;
        const float2* src = (const float2*)(g_rep + ((long)w * M_ + m) * CE_);
        float2* dst = (float2*)(g_xcat + ((long)b * L_ + pos) * 128 + CE_);
        dst[lane] = src[lane];
    }
}

// ---------------- tf32 tensor-core GEMM: C = A @ Bt^T + bias -----------------
// A [M,K] row-major, Bt [N,K] row-major, mma.m16n8k8.tf32, CTA tile 128x128,
// BK=16, 8 warps 4(m)x2(n). Double-buffered smem: one barrier per k-tile,
// STS of next tile overlaps mma on current.
#define GSTR 20   // padded smem row stride in floats
#define GBUF (128 * GSTR)

static __device__ __forceinline__ void ldsm_x4(unsigned& r0, unsigned& r1,
                                               unsigned& r2, unsigned& r3, unsigned addr) {
    asm volatile("ldmatrix.sync.aligned.m8n8.x4.shared.b16 {%0,%1,%2,%3}, [%4];"
                 : "=r"(r0), "=r"(r1), "=r"(r2), "=r"(r3) : "r"(addr));
}
static __device__ __forceinline__ void ldsm_x2(unsigned& r0, unsigned& r1, unsigned addr) {
    asm volatile("ldmatrix.sync.aligned.m8n8.x2.shared.b16 {%0,%1}, [%2];"
                 : "=r"(r0), "=r"(r1) : "r"(addr));
}
static __device__ __forceinline__ void mma_tf32(float* c, const unsigned* a, const unsigned* b) {
    asm volatile("mma.sync.aligned.m16n8k8.row.col.f32.tf32.tf32.f32 "
                 "{%0,%1,%2,%3}, {%4,%5,%6,%7}, {%8,%9}, {%0,%1,%2,%3};"
                 : "+f"(c[0]), "+f"(c[1]), "+f"(c[2]), "+f"(c[3])
                 : "r"(a[0]), "r"(a[1]), "r"(a[2]), "r"(a[3]), "r"(b[0]), "r"(b[1]));
}

__global__ __launch_bounds__(256)
void tf32_gemm_kernel(int M, int N, int K,
                      const float* __restrict__ A,
                      const float* __restrict__ Bt,
                      const float* __restrict__ bias,
                      float* __restrict__ C) {
    __shared__ unsigned As[2][GBUF];
    __shared__ unsigned Bs[2][GBUF];
    int tid = threadIdx.x, lane = tid & 31, wid = tid >> 5;
    int bm = blockIdx.y, bn = blockIdx.x;
    int wm = (wid >> 1) * 32;
    int wn = (wid & 1) * 64;

    int lr = tid >> 2, lk = (tid & 3) * 4;
    const float* Ag0 = A  + (long)(bm * 128 + lr) * K + lk;
    const float* Ag1 = Ag0 + (long)64 * K;
    const float* Bg0 = Bt + (long)(bn * 128 + lr) * K + lk;
    const float* Bg1 = Bg0 + (long)64 * K;

    int mat = lane >> 3;
    unsigned a_off = (unsigned)(((wm + (mat & 1) * 8 + (lane & 7)) * GSTR
                                + (mat >> 1) * 4) * 4);
    unsigned b_off = (unsigned)(((wn + (lane & 7)) * GSTR + (mat & 1) * 4) * 4);
    unsigned as_base = smem_u32(As);
    unsigned bs_base = smem_u32(Bs);

    float acc[2][8][4];
    #pragma unroll
    for (int i = 0; i < 2; i++)
        #pragma unroll
        for (int j = 0; j < 8; j++)
            #pragma unroll
            for (int v = 0; v < 4; v++) acc[i][j][v] = 0.f;

    int so0 = lr * GSTR + lk;
    int so1 = (lr + 64) * GSTR + lk;

    // first tile -> buffer 0
    float4 ra0 = *(const float4*)Ag0;
    float4 ra1 = *(const float4*)Ag1;
    float4 rb0 = *(const float4*)Bg0;
    float4 rb1 = *(const float4*)Bg1;
    *(uint4*)&As[0][so0] = make_uint4(tf32_of(ra0.x), tf32_of(ra0.y), tf32_of(ra0.z), tf32_of(ra0.w));
    *(uint4*)&As[0][so1] = make_uint4(tf32_of(ra1.x), tf32_of(ra1.y), tf32_of(ra1.z), tf32_of(ra1.w));
    *(uint4*)&Bs[0][so0] = make_uint4(tf32_of(rb0.x), tf32_of(rb0.y), tf32_of(rb0.z), tf32_of(rb0.w));
    *(uint4*)&Bs[0][so1] = make_uint4(tf32_of(rb1.x), tf32_of(rb1.y), tf32_of(rb1.z), tf32_of(rb1.w));
    __syncthreads();

    int buf = 0;
    for (int k0 = 0; k0 < K; k0 += 16) {
        bool more = (k0 + 16) < K;
        if (more) {   // prefetch next tile into registers (overlaps mma)
            Ag0 += 16; Ag1 += 16; Bg0 += 16; Bg1 += 16;
            ra0 = *(const float4*)Ag0;
            ra1 = *(const float4*)Ag1;
            rb0 = *(const float4*)Bg0;
            rb1 = *(const float4*)Bg1;
        }

        unsigned abuf = as_base + (unsigned)(buf * GBUF * 4);
        unsigned bbuf = bs_base + (unsigned)(buf * GBUF * 4);
        #pragma unroll
        for (int kk = 0; kk < 2; kk++) {
            unsigned koff = kk * 32;
            unsigned a[2][4];
            #pragma unroll
            for (int i = 0; i < 2; i++)
                ldsm_x4(a[i][0], a[i][1], a[i][2], a[i][3],
                        abuf + a_off + i * (16 * GSTR * 4) + koff);
            unsigned b[8][2];
            #pragma unroll
            for (int j = 0; j < 8; j++)
                ldsm_x2(b[j][0], b[j][1],
                        bbuf + b_off + j * (8 * GSTR * 4) + koff);
            #pragma unroll
            for (int i = 0; i < 2; i++)
                #pragma unroll
                for (int j = 0; j < 8; j++)
                    mma_tf32(acc[i][j], a[i], b[j]);
        }

        if (more) {   // store into the other buffer, then single barrier
            int nb = buf ^ 1;
            *(uint4*)&As[nb][so0] = make_uint4(tf32_of(ra0.x), tf32_of(ra0.y), tf32_of(ra0.z), tf32_of(ra0.w));
            *(uint4*)&As[nb][so1] = make_uint4(tf32_of(ra1.x), tf32_of(ra1.y), tf32_of(ra1.z), tf32_of(ra1.w));
            *(uint4*)&Bs[nb][so0] = make_uint4(tf32_of(rb0.x), tf32_of(rb0.y), tf32_of(rb0.z), tf32_of(rb0.w));
            *(uint4*)&Bs[nb][so1] = make_uint4(tf32_of(rb1.x), tf32_of(rb1.y), tf32_of(rb1.z), tf32_of(rb1.w));
            __syncthreads();
            buf = nb;
        }
    }

    #pragma unroll
    for (int i = 0; i < 2; i++) {
        int r0 = bm * 128 + wm + 16 * i + (lane >> 2);
        #pragma unroll
        for (int j = 0; j < 8; j++) {
            int cb = bn * 128 + wn + 8 * j + 2 * (lane & 3);
            float2 bv = *(const float2*)(bias + cb);
            float2 o0 = make_float2(acc[i][j][0] + bv.x, acc[i][j][1] + bv.y);
            float2 o1 = make_float2(acc[i][j][2] + bv.x, acc[i][j][3] + bv.y);
            *(float2*)&C[(long)r0 * N + cb] = o0;
            *(float2*)&C[(long)(r0 + 8) * N + cb] = o1;
        }
    }
}

// ---------------- LSTM recurrence: one CTA per batch, 2-way K-split ---------
// 512 threads. Thread (q = tid>>8, i2 = tid&255) computes gate rows r0=2*i2,
// r1=2*i2+1 over k in [64q, 64q+64). smem weights stored PRE-PACKED as ull
// (direct ffma2 operand, no mov.b64 repacking); 4 independent accumulator
// chains give 2x latency slack over the FFMA2 rt-2 issue rate.
#define WSMU_N     (2 * 16 * 256)                        // ull entries [q][kp][i2]
#define PSUM_OFF   (WSMU_N * 8)                          // bytes
#define HSM_OFF    (PSUM_OFF + 2 * G4H_ * 4)
#define LSTM_SMEM  (HSM_OFF + H_ * 4 + 128)

__global__ __launch_bounds__(512, 1)
void lstm_rec_kernel(const float* __restrict__ Whh) {
    extern __shared__ char smem_raw[];
    unsigned long long* wsmu = (unsigned long long*)smem_raw;   // [2*16*256]
    float* psum = (float*)(smem_raw + PSUM_OFF);                // [2*512]
    float* h_sm = (float*)(smem_raw + HSM_OFF);                 // [128]

    int b = blockIdx.x, tid = threadIdx.x;
    int q  = tid >> 8;         // k-half
    int i2 = tid & 255;        // row-pair index
    int r0 = 2 * i2, r1 = r0 + 1;
    int kb = 64 * q;

    const float* w0base = Whh + (long)r0 * H_ + kb;
    const float* w1base = Whh + (long)r1 * H_ + kb;
    unsigned long long w0[32], w1[16];
    #pragma unroll
    for (int k2 = 0; k2 < 32; k2++) w0[k2] = ((const unsigned long long*)w0base)[k2];
    #pragma unroll
    for (int k2 = 0; k2 < 16; k2++) w1[k2] = ((const unsigned long long*)w1base)[k2];
    // r1 k rel [32,64) -> smem, pre-packed ull, k-major, lane-contiguous
    #pragma unroll
    for (int kp = 0; kp < 16; kp++)
        wsmu[(q * 16 + kp) * 256 + i2] = ((const unsigned long long*)(w1base + 32))[kp];

    float c = 0.f;
    if (tid < H_) h_sm[tid] = 0.f;
    __syncthreads();

    const float* xp = g_xpre + (long)b * L_ * G4H_ + r0;
    float2 xr = make_float2(0.f, 0.f);
    if (q == 0) xr = *(const float2*)xp;

    for (int t = 0; t < L_; t++) {
        int tn = (t + 1 < L_) ? t + 1 : t;
        float2 xnext = make_float2(0.f, 0.f);
        if (q == 0) xnext = *(const float2*)(xp + (long)tn * G4H_);

        // 4 independent accumulator chains
        unsigned long long acc0 = pack2(xr.x, 0.f);
        unsigned long long acc1 = pack2(xr.y, 0.f);
        unsigned long long acc2 = 0ull, acc3 = 0ull;
        const ulonglong2* h2 = (const ulonglong2*)(h_sm + kb);

        #pragma unroll
        for (int k4 = 0; k4 < 8; k4++) {              // k rel [0,32): both rows from regs
            ulonglong2 hv = h2[k4];
            acc0 = ffma2(hv.x, w0[2 * k4], acc0);
            acc2 = ffma2(hv.y, w0[2 * k4 + 1], acc2);
            acc1 = ffma2(hv.x, w1[2 * k4], acc1);
            acc3 = ffma2(hv.y, w1[2 * k4 + 1], acc3);
        }
        #pragma unroll
        for (int k4 = 8; k4 < 16; k4++) {             // k rel [32,64): r1 from smem (ull direct)
            ulonglong2 hv = h2[k4];
            int kp = 2 * (k4 - 8);
            unsigned long long wa = wsmu[(q * 16 + kp) * 256 + i2];
            unsigned long long wb = wsmu[(q * 16 + kp + 1) * 256 + i2];
            acc0 = ffma2(hv.x, w0[2 * k4], acc0);
            acc2 = ffma2(hv.y, w0[2 * k4 + 1], acc2);
            acc1 = ffma2(hv.x, wa, acc1);
            acc3 = ffma2(hv.y, wb, acc3);
        }
        float2 a0 = unpack2(acc0), a1 = unpack2(acc1);
        float2 a2 = unpack2(acc2), a3 = unpack2(acc3);
        *(float2*)&psum[q * G4H_ + r0] =
            make_float2((a0.x + a0.y) + (a2.x + a2.y),
                        (a1.x + a1.y) + (a3.x + a3.y));
        __syncthreads();

        if (tid < H_) {
            float gi = psum[tid]            + psum[G4H_ + tid];
            float gf = psum[H_ + tid]       + psum[G4H_ + H_ + tid];
            float gg = psum[2 * H_ + tid]   + psum[G4H_ + 2 * H_ + tid];
            float go = psum[3 * H_ + tid]   + psum[G4H_ + 3 * H_ + tid];
            float si = fast_sigmoid(gi);
            float sf = fast_sigmoid(gf);
            float tg = fast_tanh(gg);
            float so = fast_sigmoid(go);
            c = sf * c + si * tg;
            float h = so * fast_tanh(c);
            h_sm[tid] = h;
            g_hs[((long)b * L_ + t) * H_ + tid] = h;
        }
        __syncthreads();
        xr = xnext;
    }
}

// ---------------- launch ----------------------------------------------------
extern "C" void kernel_launch(void* const* d_in, const int* in_sizes, int n_in,
                              void* d_out, int out_size) {
    const float* dec_hidden = (const float*)d_in[0];
    const int*   ids        = (const int*)d_in[1];
    const int*   lens       = (const int*)d_in[2];
    const float* char_emb   = (const float*)d_in[3];
    const float* W_proj     = (const float*)d_in[4];
    const float* b_proj     = (const float*)d_in[5];
    const float* W_ih       = (const float*)d_in[6];
    const float* W_hh       = (const float*)d_in[7];
    const float* b_ih       = (const float*)d_in[8];
    const float* b_hh       = (const float*)d_in[9];
    const float* W_pred     = (const float*)d_in[10];
    const float* b_pred     = (const float*)d_in[11];
    float* out = (float*)d_out;

    float *p_rep, *p_xcat, *p_xpre, *p_hs, *p_WprojT, *p_WpredT, *p_bias2;
    cudaGetSymbolAddress((void**)&p_rep,    g_rep);
    cudaGetSymbolAddress((void**)&p_xcat,   g_xcat);
    cudaGetSymbolAddress((void**)&p_xpre,   g_xpre);
    cudaGetSymbolAddress((void**)&p_hs,     g_hs);
    cudaGetSymbolAddress((void**)&p_WprojT, g_WprojT);
    cudaGetSymbolAddress((void**)&p_WpredT, g_WpredT);
    cudaGetSymbolAddress((void**)&p_bias2,  g_bias2);

    // 0) prep: combine biases; transpose W_proj, W_pred to (N,K)
    prep_bias_kernel<<<(G4H_ + 255) / 256, 256>>>(b_ih, b_hh);
    transpose_kernel<<<dim3(G4H_ / 32, DIM_ / 32), dim3(32, 8)>>>(W_proj, p_WprojT, DIM_, G4H_);
    transpose_kernel<<<dim3(VOCAB_ / 32, H_ / 32), dim3(32, 8)>>>(W_pred, p_WpredT, H_, VOCAB_);

    // 1) word-length prefix sums
    scan_lens_kernel<<<B_, N_>>>(lens);

    // 2) proj GEMM: rep = dec_hidden @ W_proj + b_proj   [8192,768]x[768,512]
    tf32_gemm_kernel<<<dim3(G4H_ / 128, (B_ * N_) / 128), 256>>>(
        B_ * N_, G4H_, DIM_, dec_hidden, p_WprojT, b_proj, p_rep);

    // 3) build x_cat: char half + zero padded half, then ragged scatter
    build_char_kernel<<<(B_ * L_ * 32) / 256, 256>>>(ids, char_emb);
    scatter_pad_kernel<<<(B_ * N_ * 32) / 256, 256>>>(lens);

    // 4) LSTM input pre-GEMM: xpre = x_cat @ W_ih^T + (b_ih+b_hh)
    tf32_gemm_kernel<<<dim3(G4H_ / 128, (B_ * L_) / 128), 256>>>(
        B_ * L_, G4H_, 2 * CE_, p_xcat, W_ih, p_bias2, p_xpre);

    // 5) recurrence (one CTA per batch)
    cudaFuncSetAttribute(lstm_rec_kernel,
                         cudaFuncAttributeMaxDynamicSharedMemorySize, LSTM_SMEM);
    lstm_rec_kernel<<<B_, 512, LSTM_SMEM>>>(W_hh);

    // 6) prediction GEMM: out = hs @ W_pred + b_pred   [32768,128]x[128,1024]
    tf32_gemm_kernel<<<dim3(VOCAB_ / 128, (B_ * L_) / 128), 256>>>(
        B_ * L_, VOCAB_, H_, p_hs, p_WpredT, b_pred, out);
}

// round 15
// speedup vs baseline: 1.1047x; 1.1047x over previous
#include <cuda_runtime.h>
#include <cuda_bf16.h>

#define B_ 16
#define N_ 512
#define L_ 2048
#define DIM_ 768
#define M_ 8
#define CE_ 64
#define VOCAB_ 1024
#define H_ 128
#define G4H_ (4*H_)   // 512

#define CHUNK 128
#define NCHUNK (L_/CHUNK)          // 16
#define NTILE (VOCAB_/128)         // 8
#define NTILES_TOT (B_*NCHUNK*NTILE)  // 2048
#define NPRED 132

// ---------------- scratch (device globals: no allocations allowed) ----------
__device__ float g_rep [B_*N_*M_*CE_];    // [B,N,512]  word char projections
__device__ float g_xcat[B_*L_*2*CE_];     // [B,L,128]  lstm input (char | padded)
__device__ float g_xpre[B_*L_*G4H_];      // [B,L,512]  x@W_ih^T + b_ih + b_hh
__device__ float g_hs  [B_*L_*H_];        // [B,L,128]  lstm hidden states
__device__ float g_WprojT[G4H_*DIM_];     // [512,768]  W_proj transposed (N,K)
__device__ float g_WpredT[VOCAB_*H_];     // [1024,128] W_pred transposed (N,K)
__device__ float g_bias2[G4H_];           // b_ih + b_hh
__device__ int   g_woff[B_*N_];           // exclusive prefix sum of word lens
__device__ int   g_progress[B_];          // published LSTM timesteps per batch

// ---------------- f32x2 / misc helpers ---------------------------------------
static __device__ __forceinline__ unsigned long long pack2(float lo, float hi) {
    unsigned long long r;
    asm("mov.b64 %0, {%1, %2};" : "=l"(r) : "f"(lo), "f"(hi));
    return r;
}
static __device__ __forceinline__ float2 unpack2(unsigned long long v) {
    float2 r;
    asm("mov.b64 {%0, %1}, %2;" : "=f"(r.x), "=f"(r.y) : "l"(v));
    return r;
}
static __device__ __forceinline__ unsigned long long ffma2(
    unsigned long long a, unsigned long long b, unsigned long long c) {
    unsigned long long d;
    asm("fma.rn.f32x2 %0, %1, %2, %3;" : "=l"(d) : "l"(a), "l"(b), "l"(c));
    return d;
}
static __device__ __forceinline__ float fast_tanh(float x) {
    float r;
    asm("tanh.approx.f32 %0, %1;" : "=f"(r) : "f"(x));
    return r;
}
static __device__ __forceinline__ float fast_sigmoid(float x) {
    float r;
    asm("tanh.approx.f32 %0, %1;" : "=f"(r) : "f"(0.5f * x));
    return fmaf(0.5f, r, 0.5f);
}
static __device__ __forceinline__ unsigned tf32_of(float f) {
    unsigned u;
    asm("cvt.rna.tf32.f32 %0, %1;" : "=r"(u) : "f"(f));
    return u;
}
static __device__ __forceinline__ unsigned smem_u32(const void* p) {
    return (unsigned)__cvta_generic_to_shared(p);
}
static __device__ __forceinline__ int ld_acquire(const int* p) {
    int v;
    asm volatile("ld.acquire.gpu.global.b32 %0, [%1];" : "=r"(v) : "l"(p) : "memory");
    return v;
}

// ---------------- prep: combine biases, reset progress flags -----------------
__global__ void prep_bias_kernel(const float* __restrict__ b_ih,
                                 const float* __restrict__ b_hh) {
    int i = blockIdx.x * blockDim.x + threadIdx.x;
    if (i < G4H_) g_bias2[i] = b_ih[i] + b_hh[i];
    if (i < B_) g_progress[i] = 0;
}

// ---------------- tiled transpose: dst[C][R] = src[R][C] ---------------------
__global__ void transpose_kernel(const float* __restrict__ src,
                                 float* __restrict__ dst, int R, int C) {
    __shared__ float t[32][33];
    int bx = blockIdx.x * 32, by = blockIdx.y * 32;
    int x = bx + threadIdx.x;
    #pragma unroll
    for (int dy = 0; dy < 32; dy += 8)
        t[threadIdx.y + dy][threadIdx.x] = src[(long)(by + threadIdx.y + dy) * C + x];
    __syncthreads();
    int x2 = by + threadIdx.x;
    #pragma unroll
    for (int dy = 0; dy < 32; dy += 8)
        dst[(long)(bx + threadIdx.y + dy) * R + x2] = t[threadIdx.x][threadIdx.y + dy];
}

// ---------------- per-batch exclusive prefix sum of word lens ---------------
__global__ void scan_lens_kernel(const int* __restrict__ lens) {
    __shared__ int s[N_];
    int b = blockIdx.x, tid = threadIdx.x;
    int v0 = lens[b * N_ + tid];
    s[tid] = v0;
    __syncthreads();
    #pragma unroll
    for (int off = 1; off < N_; off <<= 1) {
        int v = (tid >= off) ? s[tid - off] : 0;
        __syncthreads();
        s[tid] += v;
        __syncthreads();
    }
    g_woff[b * N_ + tid] = s[tid] - v0;   // exclusive
}

// ---------------- build x_cat: char embedding + zero padded half ------------
__global__ void build_char_kernel(const int* __restrict__ ids,
                                  const float* __restrict__ emb) {
    long i = (long)blockIdx.x * blockDim.x + threadIdx.x;   // one float4 each
    if (i >= (long)B_ * L_ * 32) return;
    int q = (int)(i & 31);
    long bt = i >> 5;
    float4* dst = (float4*)(g_xcat + bt * 128);
    if (q < 16) {
        int id = ids[bt];
        dst[q] = ((const float4*)(emb + (long)id * CE_))[q];
    } else {
        dst[q] = make_float4(0.f, 0.f, 0.f, 0.f);
    }
}

// ---------------- ragged scatter of word char projections -------------------
__global__ void scatter_pad_kernel(const int* __restrict__ lens) {
    int w = (blockIdx.x * blockDim.x + threadIdx.x) >> 5;   // one warp per word
    int lane = threadIdx.x & 31;
    if (w >= B_ * N_) return;
    int b = w / N_;
    int len = lens[w];
    int off = g_woff[w];
    for (int m = 0; m < len; m++) {
        int pos = off + m;
        if (pos >= L_) break;
        const float2* src = (const float2*)(g_rep + ((long)w * M_ + m) * CE_);
        float2* dst = (float2*)(g_xcat + ((long)b * L_ + pos) * 128 + CE_);
        dst[lane] = src[lane];
    }
}

// ---------------- tf32 tensor-core GEMM: C = A @ Bt^T + bias -----------------
// Single-buffer version as benched at 1718us. CTA 128x128, BK=16, 8 warps.
#define GSTR 20
#define GBUF (128 * GSTR)

static __device__ __forceinline__ void ldsm_x4(unsigned& r0, unsigned& r1,
                                               unsigned& r2, unsigned& r3, unsigned addr) {
    asm volatile("ldmatrix.sync.aligned.m8n8.x4.shared.b16 {%0,%1,%2,%3}, [%4];"
                 : "=r"(r0), "=r"(r1), "=r"(r2), "=r"(r3) : "r"(addr));
}
static __device__ __forceinline__ void ldsm_x2(unsigned& r0, unsigned& r1, unsigned addr) {
    asm volatile("ldmatrix.sync.aligned.m8n8.x2.shared.b16 {%0,%1}, [%2];"
                 : "=r"(r0), "=r"(r1) : "r"(addr));
}
static __device__ __forceinline__ void mma_tf32(float* c, const unsigned* a, const unsigned* b) {
    asm volatile("mma.sync.aligned.m16n8k8.row.col.f32.tf32.tf32.f32 "
                 "{%0,%1,%2,%3}, {%4,%5,%6,%7}, {%8,%9}, {%0,%1,%2,%3};"
                 : "+f"(c[0]), "+f"(c[1]), "+f"(c[2]), "+f"(c[3])
                 : "r"(a[0]), "r"(a[1]), "r"(a[2]), "r"(a[3]), "r"(b[0]), "r"(b[1]));
}

__global__ __launch_bounds__(256)
void tf32_gemm_kernel(int M, int N, int K,
                      const float* __restrict__ A,
                      const float* __restrict__ Bt,
                      const float* __restrict__ bias,
                      float* __restrict__ C) {
    __shared__ unsigned As[GBUF];
    __shared__ unsigned Bs[GBUF];
    int tid = threadIdx.x, lane = tid & 31, wid = tid >> 5;
    int bm = blockIdx.y, bn = blockIdx.x;
    int wm = (wid >> 1) * 32;
    int wn = (wid & 1) * 64;

    int lr = tid >> 2, lk = (tid & 3) * 4;
    const float* Ag0 = A  + (long)(bm * 128 + lr) * K + lk;
    const float* Ag1 = Ag0 + (long)64 * K;
    const float* Bg0 = Bt + (long)(bn * 128 + lr) * K + lk;
    const float* Bg1 = Bg0 + (long)64 * K;

    int mat = lane >> 3;
    unsigned a_off = (unsigned)(((wm + (mat & 1) * 8 + (lane & 7)) * GSTR
                                + (mat >> 1) * 4) * 4);
    unsigned b_off = (unsigned)(((wn + (lane & 7)) * GSTR + (mat & 1) * 4) * 4);
    unsigned as_base = smem_u32(As);
    unsigned bs_base = smem_u32(Bs);

    float acc[2][8][4];
    #pragma unroll
    for (int i = 0; i < 2; i++)
        #pragma unroll
        for (int j = 0; j < 8; j++)
            #pragma unroll
            for (int v = 0; v < 4; v++) acc[i][j][v] = 0.f;

    float4 ra0 = *(const float4*)Ag0;
    float4 ra1 = *(const float4*)Ag1;
    float4 rb0 = *(const float4*)Bg0;
    float4 rb1 = *(const float4*)Bg1;

    unsigned* AsW0 = As + lr * GSTR + lk;
    unsigned* AsW1 = As + (lr + 64) * GSTR + lk;
    unsigned* BsW0 = Bs + lr * GSTR + lk;
    unsigned* BsW1 = Bs + (lr + 64) * GSTR + lk;

    for (int k0 = 0; k0 < K; k0 += 16) {
        __syncthreads();
        *(uint4*)AsW0 = make_uint4(tf32_of(ra0.x), tf32_of(ra0.y), tf32_of(ra0.z), tf32_of(ra0.w));
        *(uint4*)AsW1 = make_uint4(tf32_of(ra1.x), tf32_of(ra1.y), tf32_of(ra1.z), tf32_of(ra1.w));
        *(uint4*)BsW0 = make_uint4(tf32_of(rb0.x), tf32_of(rb0.y), tf32_of(rb0.z), tf32_of(rb0.w));
        *(uint4*)BsW1 = make_uint4(tf32_of(rb1.x), tf32_of(rb1.y), tf32_of(rb1.z), tf32_of(rb1.w));
        __syncthreads();

        if (k0 + 16 < K) {
            Ag0 += 16; Ag1 += 16; Bg0 += 16; Bg1 += 16;
            ra0 = *(const float4*)Ag0;
            ra1 = *(const float4*)Ag1;
            rb0 = *(const float4*)Bg0;
            rb1 = *(const float4*)Bg1;
        }

        #pragma unroll
        for (int kk = 0; kk < 2; kk++) {
            unsigned koff = kk * 32;
            unsigned a[2][4];
            #pragma unroll
            for (int i = 0; i < 2; i++)
                ldsm_x4(a[i][0], a[i][1], a[i][2], a[i][3],
                        as_base + a_off + i * (16 * GSTR * 4) + koff);
            unsigned b[8][2];
            #pragma unroll
            for (int j = 0; j < 8; j++)
                ldsm_x2(b[j][0], b[j][1],
                        bs_base + b_off + j * (8 * GSTR * 4) + koff);
            #pragma unroll
            for (int i = 0; i < 2; i++)
                #pragma unroll
                for (int j = 0; j < 8; j++)
                    mma_tf32(acc[i][j], a[i], b[j]);
        }
    }

    #pragma unroll
    for (int i = 0; i < 2; i++) {
        int r0 = bm * 128 + wm + 16 * i + (lane >> 2);
        #pragma unroll
        for (int j = 0; j < 8; j++) {
            int cb = bn * 128 + wn + 8 * j + 2 * (lane & 3);
            float2 bv = *(const float2*)(bias + cb);
            float2 o0 = make_float2(acc[i][j][0] + bv.x, acc[i][j][1] + bv.y);
            float2 o1 = make_float2(acc[i][j][2] + bv.x, acc[i][j][3] + bv.y);
            *(float2*)&C[(long)r0 * N + cb] = o0;
            *(float2*)&C[(long)(r0 + 8) * N + cb] = o1;
        }
    }
}

// ---------------- pred GEMM tile as device function (consumer side) ----------
// 128x128x128 tile; 512 threads call it, first 256 do the work (barriers by all).
static __device__ void pred_tile(const float* __restrict__ A,    // g_hs [.,128]
                                 const float* __restrict__ Bt,   // WpredT [1024,128]
                                 const float* __restrict__ bias,
                                 float* __restrict__ C,
                                 int mbase, int nbase,
                                 unsigned* As, unsigned* Bs, int tid) {
    bool act = tid < 256;
    int lane = tid & 31, wid8 = (tid >> 5) & 7;
    int wm = (wid8 >> 1) * 32;
    int wn = (wid8 & 1) * 64;
    int lr = (tid & 255) >> 2, lk = (tid & 3) * 4;
    int mat = lane >> 3;
    unsigned a_off = (unsigned)(((wm + (mat & 1) * 8 + (lane & 7)) * GSTR
                                + (mat >> 1) * 4) * 4);
    unsigned b_off = (unsigned)(((wn + (lane & 7)) * GSTR + (mat & 1) * 4) * 4);
    unsigned as_base = smem_u32(As);
    unsigned bs_base = smem_u32(Bs);

    float acc[2][8][4];
    #pragma unroll
    for (int i = 0; i < 2; i++)
        #pragma unroll
        for (int j = 0; j < 8; j++)
            #pragma unroll
            for (int v = 0; v < 4; v++) acc[i][j][v] = 0.f;

    const float* Ag0 = A + (long)(mbase + lr) * H_ + lk;
    const float* Ag1 = Ag0 + (long)64 * H_;
    const float* Bg0 = Bt + (long)(nbase + lr) * H_ + lk;
    const float* Bg1 = Bg0 + (long)64 * H_;
    unsigned* AsW0 = As + lr * GSTR + lk;
    unsigned* AsW1 = As + (lr + 64) * GSTR + lk;
    unsigned* BsW0 = Bs + lr * GSTR + lk;
    unsigned* BsW1 = Bs + (lr + 64) * GSTR + lk;

    for (int k0 = 0; k0 < H_; k0 += 16) {
        __syncthreads();
        if (act) {
            float4 ra0 = __ldcg((const float4*)(Ag0 + k0));
            float4 ra1 = __ldcg((const float4*)(Ag1 + k0));
            float4 rb0 = *(const float4*)(Bg0 + k0);
            float4 rb1 = *(const float4*)(Bg1 + k0);
            *(uint4*)AsW0 = make_uint4(tf32_of(ra0.x), tf32_of(ra0.y), tf32_of(ra0.z), tf32_of(ra0.w));
            *(uint4*)AsW1 = make_uint4(tf32_of(ra1.x), tf32_of(ra1.y), tf32_of(ra1.z), tf32_of(ra1.w));
            *(uint4*)BsW0 = make_uint4(tf32_of(rb0.x), tf32_of(rb0.y), tf32_of(rb0.z), tf32_of(rb0.w));
            *(uint4*)BsW1 = make_uint4(tf32_of(rb1.x), tf32_of(rb1.y), tf32_of(rb1.z), tf32_of(rb1.w));
        }
        __syncthreads();
        if (act) {
            #pragma unroll
            for (int kk = 0; kk < 2; kk++) {
                unsigned koff = kk * 32;
                unsigned a[2][4];
                #pragma unroll
                for (int i = 0; i < 2; i++)
                    ldsm_x4(a[i][0], a[i][1], a[i][2], a[i][3],
                            as_base + a_off + i * (16 * GSTR * 4) + koff);
                unsigned b[8][2];
                #pragma unroll
                for (int j = 0; j < 8; j++)
                    ldsm_x2(b[j][0], b[j][1],
                            bs_base + b_off + j * (8 * GSTR * 4) + koff);
                #pragma unroll
                for (int i = 0; i < 2; i++)
                    #pragma unroll
                    for (int j = 0; j < 8; j++)
                        mma_tf32(acc[i][j], a[i], b[j]);
            }
        }
    }

    if (act) {
        #pragma unroll
        for (int i = 0; i < 2; i++) {
            int r0 = mbase + wm + 16 * i + (lane >> 2);
            #pragma unroll
            for (int j = 0; j < 8; j++) {
                int cb = nbase + wn + 8 * j + 2 * (lane & 3);
                float2 bv = *(const float2*)(bias + cb);
                float2 o0 = make_float2(acc[i][j][0] + bv.x, acc[i][j][1] + bv.y);
                float2 o1 = make_float2(acc[i][j][2] + bv.x, acc[i][j][3] + bv.y);
                *(float2*)&C[(long)r0 * VOCAB_ + cb] = o0;
                *(float2*)&C[(long)(r0 + 8) * VOCAB_ + cb] = o1;
            }
        }
    }
}

// ---------------- fused recurrence + pred GEMM (producer/consumer) -----------
// blockIdx < 16: LSTM recurrence (exact 1718us-benched version + publish).
// blockIdx >= 16: persistent consumers computing out = hs @ W_pred^T + b_pred
// tile-by-tile as chunks of hs are published.
#define WSM2_FLOAT2 (2 * 16 * 256)                       // [q][kp][i2]
#define PSUM_OFF    (WSM2_FLOAT2 * 8)                    // bytes
#define HSM_OFF     (PSUM_OFF + 2 * G4H_ * 4)
#define LSTM_SMEM   (HSM_OFF + H_ * 4 + 128)

__global__ __launch_bounds__(512, 1)
void fused_rec_pred_kernel(const float* __restrict__ Whh,
                           const float* __restrict__ WpredT,
                           const float* __restrict__ b_pred,
                           float* __restrict__ out) {
    extern __shared__ char smem_raw[];
    int tid = threadIdx.x;

    if (blockIdx.x < B_) {
        // ================= recurrence producer =================
        float2* wsm2 = (float2*)smem_raw;                    // [2*16*256]
        float*  psum = (float*)(smem_raw + PSUM_OFF);        // [2*512]
        float*  h_sm = (float*)(smem_raw + HSM_OFF);         // [128]

        int b = blockIdx.x;
        int q  = tid >> 8;         // k-half
        int i2 = tid & 255;        // row-pair index
        int r0 = 2 * i2, r1 = r0 + 1;
        int kb = 64 * q;

        const float* w0base = Whh + (long)r0 * H_ + kb;
        const float* w1base = Whh + (long)r1 * H_ + kb;
        unsigned long long w0[32], w1[16];
        #pragma unroll
        for (int k2 = 0; k2 < 32; k2++) w0[k2] = ((const unsigned long long*)w0base)[k2];
        #pragma unroll
        for (int k2 = 0; k2 < 16; k2++) w1[k2] = ((const unsigned long long*)w1base)[k2];
        #pragma unroll
        for (int kp = 0; kp < 16; kp++)
            wsm2[(q * 16 + kp) * 256 + i2] = ((const float2*)(w1base + 32))[kp];

        float c = 0.f;
        if (tid < H_) h_sm[tid] = 0.f;
        __syncthreads();

        const float* xp = g_xpre + (long)b * L_ * G4H_ + r0;
        float2 xr = make_float2(0.f, 0.f);
        if (q == 0) xr = *(const float2*)xp;

        for (int t = 0; t < L_; t++) {
            int tn = (t + 1 < L_) ? t + 1 : t;
            float2 xnext = make_float2(0.f, 0.f);
            if (q == 0) xnext = *(const float2*)(xp + (long)tn * G4H_);

            unsigned long long acc0 = pack2(xr.x, 0.f);
            unsigned long long acc1 = pack2(xr.y, 0.f);
            const ulonglong2* h2 = (const ulonglong2*)(h_sm + kb);

            #pragma unroll
            for (int k4 = 0; k4 < 8; k4++) {
                ulonglong2 hv = h2[k4];
                acc0 = ffma2(hv.x, w0[2 * k4], acc0);
                acc0 = ffma2(hv.y, w0[2 * k4 + 1], acc0);
                acc1 = ffma2(hv.x, w1[2 * k4], acc1);
                acc1 = ffma2(hv.y, w1[2 * k4 + 1], acc1);
            }
            #pragma unroll
            for (int k4 = 8; k4 < 16; k4++) {
                ulonglong2 hv = h2[k4];
                int kp = 2 * (k4 - 8);
                float2 wa = wsm2[(q * 16 + kp) * 256 + i2];
                float2 wb = wsm2[(q * 16 + kp + 1) * 256 + i2];
                acc0 = ffma2(hv.x, w0[2 * k4], acc0);
                acc0 = ffma2(hv.y, w0[2 * k4 + 1], acc0);
                acc1 = ffma2(hv.x, pack2(wa.x, wa.y), acc1);
                acc1 = ffma2(hv.y, pack2(wb.x, wb.y), acc1);
            }
            float2 a0 = unpack2(acc0), a1 = unpack2(acc1);
            *(float2*)&psum[q * G4H_ + r0] = make_float2(a0.x + a0.y, a1.x + a1.y);
            __syncthreads();

            if (tid < H_) {
                float gi = psum[tid]            + psum[G4H_ + tid];
                float gf = psum[H_ + tid]       + psum[G4H_ + H_ + tid];
                float gg = psum[2 * H_ + tid]   + psum[G4H_ + 2 * H_ + tid];
                float go = psum[3 * H_ + tid]   + psum[G4H_ + 3 * H_ + tid];
                float si = fast_sigmoid(gi);
                float sf = fast_sigmoid(gf);
                float tg = fast_tanh(gg);
                float so = fast_sigmoid(go);
                c = sf * c + si * tg;
                float h = so * fast_tanh(c);
                h_sm[tid] = h;
                g_hs[((long)b * L_ + t) * H_ + tid] = h;
            }
            __syncthreads();

            // publish completed chunk (release: CTA barrier + gpu fence + atomic)
            if (((t & (CHUNK - 1)) == (CHUNK - 1)) && tid == 0) {
                __threadfence();
                atomicExch(&g_progress[b], t + 1);
            }
            xr = xnext;
        }
    } else {
        // ================= pred GEMM consumers =================
        unsigned* As = (unsigned*)smem_raw;          // [GBUF]
        unsigned* Bs = As + GBUF;                    // [GBUF]
        int cta = blockIdx.x - B_;

        for (int idx = cta; idx < NTILES_TOT; idx += NPRED) {
            int cchunk = idx / (B_ * NTILE);
            int rem    = idx % (B_ * NTILE);
            int b      = rem / NTILE;
            int nt     = rem % NTILE;

            if (tid == 0) {
                int need = (cchunk + 1) * CHUNK;
                while (ld_acquire(&g_progress[b]) < need) __nanosleep(200);
            }
            __syncthreads();   // propagate acquire to whole CTA

            int mbase = b * L_ + cchunk * CHUNK;
            int nbase = nt * 128;
            pred_tile(g_hs, WpredT, b_pred, out, mbase, nbase, As, Bs, tid);
        }
    }
}

// ---------------- launch ----------------------------------------------------
extern "C" void kernel_launch(void* const* d_in, const int* in_sizes, int n_in,
                              void* d_out, int out_size) {
    const float* dec_hidden = (const float*)d_in[0];
    const int*   ids        = (const int*)d_in[1];
    const int*   lens       = (const int*)d_in[2];
    const float* char_emb   = (const float*)d_in[3];
    const float* W_proj     = (const float*)d_in[4];
    const float* b_proj     = (const float*)d_in[5];
    const float* W_ih       = (const float*)d_in[6];
    const float* W_hh       = (const float*)d_in[7];
    const float* b_ih       = (const float*)d_in[8];
    const float* b_hh       = (const float*)d_in[9];
    const float* W_pred     = (const float*)d_in[10];
    const float* b_pred     = (const float*)d_in[11];
    float* out = (float*)d_out;

    float *p_rep, *p_xcat, *p_xpre, *p_WprojT, *p_WpredT, *p_bias2;
    cudaGetSymbolAddress((void**)&p_rep,    g_rep);
    cudaGetSymbolAddress((void**)&p_xcat,   g_xcat);
    cudaGetSymbolAddress((void**)&p_xpre,   g_xpre);
    cudaGetSymbolAddress((void**)&p_WprojT, g_WprojT);
    cudaGetSymbolAddress((void**)&p_WpredT, g_WpredT);
    cudaGetSymbolAddress((void**)&p_bias2,  g_bias2);

    // 0) prep: combine biases + reset progress; transpose W_proj, W_pred
    prep_bias_kernel<<<(G4H_ + 255) / 256, 256>>>(b_ih, b_hh);
    transpose_kernel<<<dim3(G4H_ / 32, DIM_ / 32), dim3(32, 8)>>>(W_proj, p_WprojT, DIM_, G4H_);
    transpose_kernel<<<dim3(VOCAB_ / 32, H_ / 32), dim3(32, 8)>>>(W_pred, p_WpredT, H_, VOCAB_);

    // 1) word-length prefix sums
    scan_lens_kernel<<<B_, N_>>>(lens);

    // 2) proj GEMM: rep = dec_hidden @ W_proj + b_proj   [8192,768]x[768,512]
    tf32_gemm_kernel<<<dim3(G4H_ / 128, (B_ * N_) / 128), 256>>>(
        B_ * N_, G4H_, DIM_, dec_hidden, p_WprojT, b_proj, p_rep);

    // 3) build x_cat: char half + zero padded half, then ragged scatter
    build_char_kernel<<<(B_ * L_ * 32) / 256, 256>>>(ids, char_emb);
    scatter_pad_kernel<<<(B_ * N_ * 32) / 256, 256>>>(lens);

    // 4) LSTM input pre-GEMM: xpre = x_cat @ W_ih^T + (b_ih+b_hh)
    tf32_gemm_kernel<<<dim3(G4H_ / 128, (B_ * L_) / 128), 256>>>(
        B_ * L_, G4H_, 2 * CE_, p_xcat, W_ih, p_bias2, p_xpre);

    // 5+6) fused: recurrence (16 producer CTAs) + pred GEMM (132 consumers)
    cudaFuncSetAttribute(fused_rec_pred_kernel,
                         cudaFuncAttributeMaxDynamicSharedMemorySize, LSTM_SMEM);
    fused_rec_pred_kernel<<<B_ + NPRED, 512, LSTM_SMEM>>>(W_hh, p_WpredT, b_pred, out);
}

// round 17
// speedup vs baseline: 1.1737x; 1.0625x over previous
#include <cuda_runtime.h>
#include <cuda_bf16.h>

#define B_ 16
#define N_ 512
#define L_ 2048
#define DIM_ 768
#define M_ 8
#define CE_ 64
#define VOCAB_ 1024
#define H_ 128
#define G4H_ (4*H_)   // 512

#define CHUNK 128
#define NCHUNK (L_/CHUNK)             // 16
#define NTILE (VOCAB_/128)            // 8
#define NTILES_TOT (B_*NCHUNK*NTILE)  // 2048 pred tiles
#define NXTILE 4                      // xpre N tiles (512/128)
#define NXTILES_TOT (B_*NCHUNK*NXTILE) // 1024 xpre tiles
#define NPRED 132

// ---------------- scratch (device globals: no allocations allowed) ----------
__device__ float g_rep [B_*N_*M_*CE_];    // [B,N,512]  word char projections
__device__ float g_xcat[B_*L_*2*CE_];     // [B,L,128]  lstm input (char | padded)
__device__ float g_xpre[B_*L_*G4H_];      // [B,L,512]  x@W_ih^T + b_ih + b_hh
__device__ float g_hs  [B_*L_*H_];        // [B,L,128]  lstm hidden states
__device__ float g_WprojT[G4H_*DIM_];     // [512,768]  W_proj transposed (N,K)
__device__ float g_WpredT[VOCAB_*H_];     // [1024,128] W_pred transposed (N,K)
__device__ float g_bias2[G4H_];           // b_ih + b_hh
__device__ int   g_woff[B_*N_];           // exclusive prefix sum of word lens
__device__ int   g_progress[B_];          // published LSTM timesteps per batch
__device__ int   g_xcnt[B_*NCHUNK];       // finished xpre tiles per (b,chunk)
__device__ int   g_xdone[B_*NCHUNK];      // xpre chunk complete flag

// ---------------- f32x2 / misc helpers ---------------------------------------
static __device__ __forceinline__ unsigned long long pack2(float lo, float hi) {
    unsigned long long r;
    asm("mov.b64 %0, {%1, %2};" : "=l"(r) : "f"(lo), "f"(hi));
    return r;
}
static __device__ __forceinline__ float2 unpack2(unsigned long long v) {
    float2 r;
    asm("mov.b64 {%0, %1}, %2;" : "=f"(r.x), "=f"(r.y) : "l"(v));
    return r;
}
static __device__ __forceinline__ unsigned long long ffma2(
    unsigned long long a, unsigned long long b, unsigned long long c) {
    unsigned long long d;
    asm("fma.rn.f32x2 %0, %1, %2, %3;" : "=l"(d) : "l"(a), "l"(b), "l"(c));
    return d;
}
static __device__ __forceinline__ float fast_tanh(float x) {
    float r;
    asm("tanh.approx.f32 %0, %1;" : "=f"(r) : "f"(x));
    return r;
}
static __device__ __forceinline__ float fast_sigmoid(float x) {
    float r;
    asm("tanh.approx.f32 %0, %1;" : "=f"(r) : "f"(0.5f * x));
    return fmaf(0.5f, r, 0.5f);
}
static __device__ __forceinline__ unsigned tf32_of(float f) {
    unsigned u;
    asm("cvt.rna.tf32.f32 %0, %1;" : "=r"(u) : "f"(f));
    return u;
}
static __device__ __forceinline__ unsigned smem_u32(const void* p) {
    return (unsigned)__cvta_generic_to_shared(p);
}
static __device__ __forceinline__ int ld_acquire(const int* p) {
    int v;
    asm volatile("ld.acquire.gpu.global.b32 %0, [%1];" : "=r"(v) : "l"(p) : "memory");
    return v;
}

// ---------------- prep: combine biases, reset sync state ---------------------
__global__ void prep_bias_kernel(const float* __restrict__ b_ih,
                                 const float* __restrict__ b_hh) {
    int i = blockIdx.x * blockDim.x + threadIdx.x;
    if (i < G4H_) g_bias2[i] = b_ih[i] + b_hh[i];
    if (i < B_) g_progress[i] = 0;
    if (i < B_ * NCHUNK) { g_xcnt[i] = 0; g_xdone[i] = 0; }
}

// ---------------- tiled transpose: dst[C][R] = src[R][C] ---------------------
__global__ void transpose_kernel(const float* __restrict__ src,
                                 float* __restrict__ dst, int R, int C) {
    __shared__ float t[32][33];
    int bx = blockIdx.x * 32, by = blockIdx.y * 32;
    int x = bx + threadIdx.x;
    #pragma unroll
    for (int dy = 0; dy < 32; dy += 8)
        t[threadIdx.y + dy][threadIdx.x] = src[(long)(by + threadIdx.y + dy) * C + x];
    __syncthreads();
    int x2 = by + threadIdx.x;
    #pragma unroll
    for (int dy = 0; dy < 32; dy += 8)
        dst[(long)(bx + threadIdx.y + dy) * R + x2] = t[threadIdx.x][threadIdx.y + dy];
}

// ---------------- per-batch exclusive prefix sum of word lens ---------------
__global__ void scan_lens_kernel(const int* __restrict__ lens) {
    __shared__ int s[N_];
    int b = blockIdx.x, tid = threadIdx.x;
    int v0 = lens[b * N_ + tid];
    s[tid] = v0;
    __syncthreads();
    #pragma unroll
    for (int off = 1; off < N_; off <<= 1) {
        int v = (tid >= off) ? s[tid - off] : 0;
        __syncthreads();
        s[tid] += v;
        __syncthreads();
    }
    g_woff[b * N_ + tid] = s[tid] - v0;   // exclusive
}

// ---------------- build x_cat: char embedding + zero padded half ------------
__global__ void build_char_kernel(const int* __restrict__ ids,
                                  const float* __restrict__ emb) {
    long i = (long)blockIdx.x * blockDim.x + threadIdx.x;   // one float4 each
    if (i >= (long)B_ * L_ * 32) return;
    int q = (int)(i & 31);
    long bt = i >> 5;
    float4* dst = (float4*)(g_xcat + bt * 128);
    if (q < 16) {
        int id = ids[bt];
        dst[q] = ((const float4*)(emb + (long)id * CE_))[q];
    } else {
        dst[q] = make_float4(0.f, 0.f, 0.f, 0.f);
    }
}

// ---------------- ragged scatter of word char projections -------------------
__global__ void scatter_pad_kernel(const int* __restrict__ lens) {
    int w = (blockIdx.x * blockDim.x + threadIdx.x) >> 5;   // one warp per word
    int lane = threadIdx.x & 31;
    if (w >= B_ * N_) return;
    int b = w / N_;
    int len = lens[w];
    int off = g_woff[w];
    for (int m = 0; m < len; m++) {
        int pos = off + m;
        if (pos >= L_) break;
        const float2* src = (const float2*)(g_rep + ((long)w * M_ + m) * CE_);
        float2* dst = (float2*)(g_xcat + ((long)b * L_ + pos) * 128 + CE_);
        dst[lane] = src[lane];
    }
}

// ---------------- tf32 tensor-core GEMM: C = A @ Bt^T + bias -----------------
#define GSTR 20
#define GBUF (128 * GSTR)

static __device__ __forceinline__ void ldsm_x4(unsigned& r0, unsigned& r1,
                                               unsigned& r2, unsigned& r3, unsigned addr) {
    asm volatile("ldmatrix.sync.aligned.m8n8.x4.shared.b16 {%0,%1,%2,%3}, [%4];"
                 : "=r"(r0), "=r"(r1), "=r"(r2), "=r"(r3) : "r"(addr));
}
static __device__ __forceinline__ void ldsm_x2(unsigned& r0, unsigned& r1, unsigned addr) {
    asm volatile("ldmatrix.sync.aligned.m8n8.x2.shared.b16 {%0,%1}, [%2];"
                 : "=r"(r0), "=r"(r1) : "r"(addr));
}
static __device__ __forceinline__ void mma_tf32(float* c, const unsigned* a, const unsigned* b) {
    asm volatile("mma.sync.aligned.m16n8k8.row.col.f32.tf32.tf32.f32 "
                 "{%0,%1,%2,%3}, {%4,%5,%6,%7}, {%8,%9}, {%0,%1,%2,%3};"
                 : "+f"(c[0]), "+f"(c[1]), "+f"(c[2]), "+f"(c[3])
                 : "r"(a[0]), "r"(a[1]), "r"(a[2]), "r"(a[3]), "r"(b[0]), "r"(b[1]));
}

__global__ __launch_bounds__(256)
void tf32_gemm_kernel(int M, int N, int K,
                      const float* __restrict__ A,
                      const float* __restrict__ Bt,
                      const float* __restrict__ bias,
                      float* __restrict__ C) {
    __shared__ unsigned As[GBUF];
    __shared__ unsigned Bs[GBUF];
    int tid = threadIdx.x, lane = tid & 31, wid = tid >> 5;
    int bm = blockIdx.y, bn = blockIdx.x;
    int wm = (wid >> 1) * 32;
    int wn = (wid & 1) * 64;

    int lr = tid >> 2, lk = (tid & 3) * 4;
    const float* Ag0 = A  + (long)(bm * 128 + lr) * K + lk;
    const float* Ag1 = Ag0 + (long)64 * K;
    const float* Bg0 = Bt + (long)(bn * 128 + lr) * K + lk;
    const float* Bg1 = Bg0 + (long)64 * K;

    int mat = lane >> 3;
    unsigned a_off = (unsigned)(((wm + (mat & 1) * 8 + (lane & 7)) * GSTR
                                + (mat >> 1) * 4) * 4);
    unsigned b_off = (unsigned)(((wn + (lane & 7)) * GSTR + (mat & 1) * 4) * 4);
    unsigned as_base = smem_u32(As);
    unsigned bs_base = smem_u32(Bs);

    float acc[2][8][4];
    #pragma unroll
    for (int i = 0; i < 2; i++)
        #pragma unroll
        for (int j = 0; j < 8; j++)
            #pragma unroll
            for (int v = 0; v < 4; v++) acc[i][j][v] = 0.f;

    float4 ra0 = *(const float4*)Ag0;
    float4 ra1 = *(const float4*)Ag1;
    float4 rb0 = *(const float4*)Bg0;
    float4 rb1 = *(const float4*)Bg1;

    unsigned* AsW0 = As + lr * GSTR + lk;
    unsigned* AsW1 = As + (lr + 64) * GSTR + lk;
    unsigned* BsW0 = Bs + lr * GSTR + lk;
    unsigned* BsW1 = Bs + (lr + 64) * GSTR + lk;

    for (int k0 = 0; k0 < K; k0 += 16) {
        __syncthreads();
        *(uint4*)AsW0 = make_uint4(tf32_of(ra0.x), tf32_of(ra0.y), tf32_of(ra0.z), tf32_of(ra0.w));
        *(uint4*)AsW1 = make_uint4(tf32_of(ra1.x), tf32_of(ra1.y), tf32_of(ra1.z), tf32_of(ra1.w));
        *(uint4*)BsW0 = make_uint4(tf32_of(rb0.x), tf32_of(rb0.y), tf32_of(rb0.z), tf32_of(rb0.w));
        *(uint4*)BsW1 = make_uint4(tf32_of(rb1.x), tf32_of(rb1.y), tf32_of(rb1.z), tf32_of(rb1.w));
        __syncthreads();

        if (k0 + 16 < K) {
            Ag0 += 16; Ag1 += 16; Bg0 += 16; Bg1 += 16;
            ra0 = *(const float4*)Ag0;
            ra1 = *(const float4*)Ag1;
            rb0 = *(const float4*)Bg0;
            rb1 = *(const float4*)Bg1;
        }

        #pragma unroll
        for (int kk = 0; kk < 2; kk++) {
            unsigned koff = kk * 32;
            unsigned a[2][4];
            #pragma unroll
            for (int i = 0; i < 2; i++)
                ldsm_x4(a[i][0], a[i][1], a[i][2], a[i][3],
                        as_base + a_off + i * (16 * GSTR * 4) + koff);
            unsigned b[8][2];
            #pragma unroll
            for (int j = 0; j < 8; j++)
                ldsm_x2(b[j][0], b[j][1],
                        bs_base + b_off + j * (8 * GSTR * 4) + koff);
            #pragma unroll
            for (int i = 0; i < 2; i++)
                #pragma unroll
                for (int j = 0; j < 8; j++)
                    mma_tf32(acc[i][j], a[i], b[j]);
        }
    }

    #pragma unroll
    for (int i = 0; i < 2; i++) {
        int r0 = bm * 128 + wm + 16 * i + (lane >> 2);
        #pragma unroll
        for (int j = 0; j < 8; j++) {
            int cb = bn * 128 + wn + 8 * j + 2 * (lane & 3);
            float2 bv = *(const float2*)(bias + cb);
            float2 o0 = make_float2(acc[i][j][0] + bv.x, acc[i][j][1] + bv.y);
            float2 o1 = make_float2(acc[i][j][2] + bv.x, acc[i][j][3] + bv.y);
            *(float2*)&C[(long)r0 * N + cb] = o0;
            *(float2*)&C[(long)(r0 + 8) * N + cb] = o1;
        }
    }
}

// ---------------- generic 128x128xK=128 tile (consumer side) -----------------
// A row stride = 128 floats (g_hs or g_xcat). Bt [*,128]. C row stride = ldc.
// 512 threads call it; first 256 work, all hit barriers.
static __device__ void gemm_tile_k128(const float* __restrict__ A,
                                      const float* __restrict__ Bt,
                                      const float* __restrict__ bias,
                                      float* __restrict__ C,
                                      int mbase, int nbase, int ldc,
                                      unsigned* As, unsigned* Bs, int tid) {
    bool act = tid < 256;
    int lane = tid & 31, wid8 = (tid >> 5) & 7;
    int wm = (wid8 >> 1) * 32;
    int wn = (wid8 & 1) * 64;
    int lr = (tid & 255) >> 2, lk = (tid & 3) * 4;
    int mat = lane >> 3;
    unsigned a_off = (unsigned)(((wm + (mat & 1) * 8 + (lane & 7)) * GSTR
                                + (mat >> 1) * 4) * 4);
    unsigned b_off = (unsigned)(((wn + (lane & 7)) * GSTR + (mat & 1) * 4) * 4);
    unsigned as_base = smem_u32(As);
    unsigned bs_base = smem_u32(Bs);

    float acc[2][8][4];
    #pragma unroll
    for (int i = 0; i < 2; i++)
        #pragma unroll
        for (int j = 0; j < 8; j++)
            #pragma unroll
            for (int v = 0; v < 4; v++) acc[i][j][v] = 0.f;

    const float* Ag0 = A + (long)(mbase + lr) * H_ + lk;
    const float* Ag1 = Ag0 + (long)64 * H_;
    const float* Bg0 = Bt + (long)(nbase + lr) * H_ + lk;
    const float* Bg1 = Bg0 + (long)64 * H_;
    unsigned* AsW0 = As + lr * GSTR + lk;
    unsigned* AsW1 = As + (lr + 64) * GSTR + lk;
    unsigned* BsW0 = Bs + lr * GSTR + lk;
    unsigned* BsW1 = Bs + (lr + 64) * GSTR + lk;

    for (int k0 = 0; k0 < H_; k0 += 16) {
        __syncthreads();
        if (act) {
            float4 ra0 = __ldcg((const float4*)(Ag0 + k0));
            float4 ra1 = __ldcg((const float4*)(Ag1 + k0));
            float4 rb0 = *(const float4*)(Bg0 + k0);
            float4 rb1 = *(const float4*)(Bg1 + k0);
            *(uint4*)AsW0 = make_uint4(tf32_of(ra0.x), tf32_of(ra0.y), tf32_of(ra0.z), tf32_of(ra0.w));
            *(uint4*)AsW1 = make_uint4(tf32_of(ra1.x), tf32_of(ra1.y), tf32_of(ra1.z), tf32_of(ra1.w));
            *(uint4*)BsW0 = make_uint4(tf32_of(rb0.x), tf32_of(rb0.y), tf32_of(rb0.z), tf32_of(rb0.w));
            *(uint4*)BsW1 = make_uint4(tf32_of(rb1.x), tf32_of(rb1.y), tf32_of(rb1.z), tf32_of(rb1.w));
        }
        __syncthreads();
        if (act) {
            #pragma unroll
            for (int kk = 0; kk < 2; kk++) {
                unsigned koff = kk * 32;
                unsigned a[2][4];
                #pragma unroll
                for (int i = 0; i < 2; i++)
                    ldsm_x4(a[i][0], a[i][1], a[i][2], a[i][3],
                            as_base + a_off + i * (16 * GSTR * 4) + koff);
                unsigned b[8][2];
                #pragma unroll
                for (int j = 0; j < 8; j++)
                    ldsm_x2(b[j][0], b[j][1],
                            bs_base + b_off + j * (8 * GSTR * 4) + koff);
                #pragma unroll
                for (int i = 0; i < 2; i++)
                    #pragma unroll
                    for (int j = 0; j < 8; j++)
                        mma_tf32(acc[i][j], a[i], b[j]);
            }
        }
    }

    if (act) {
        #pragma unroll
        for (int i = 0; i < 2; i++) {
            int r0 = mbase + wm + 16 * i + (lane >> 2);
            #pragma unroll
            for (int j = 0; j < 8; j++) {
                int cb = nbase + wn + 8 * j + 2 * (lane & 3);
                float2 bv = *(const float2*)(bias + cb);
                float2 o0 = make_float2(acc[i][j][0] + bv.x, acc[i][j][1] + bv.y);
                float2 o1 = make_float2(acc[i][j][2] + bv.x, acc[i][j][3] + bv.y);
                *(float2*)&C[(long)r0 * ldc + cb] = o0;
                *(float2*)&C[(long)(r0 + 8) * ldc + cb] = o1;
            }
        }
    }
}

// ---------------- fused: xpre GEMM -> recurrence -> pred GEMM ----------------
// blockIdx < 16: LSTM recurrence producer (R15-proven core), chunk-gated on
//   xpre availability (g_xdone), publishes g_progress.
// blockIdx >= 16: consumers. Phase 1: compute xpre tiles (publish g_xdone).
//   Phase 2: pred GEMM tiles gated on g_progress.
#define WSM2_FLOAT2 (2 * 16 * 256)                       // [q][kp][i2]
#define PSUM_OFF    (WSM2_FLOAT2 * 8)                    // bytes
#define HSM_OFF     (PSUM_OFF + 2 * G4H_ * 4)
#define LSTM_SMEM   (HSM_OFF + H_ * 4 + 128)

__global__ __launch_bounds__(512, 1)
void fused_rec_pred_kernel(const float* __restrict__ Whh,
                           const float* __restrict__ Wih,
                           const float* __restrict__ WpredT,
                           const float* __restrict__ b_pred,
                           float* __restrict__ out) {
    extern __shared__ char smem_raw[];
    int tid = threadIdx.x;

    if (blockIdx.x < B_) {
        // ================= recurrence producer =================
        float2* wsm2 = (float2*)smem_raw;                    // [2*16*256]
        float*  psum = (float*)(smem_raw + PSUM_OFF);        // [2*512]
        float*  h_sm = (float*)(smem_raw + HSM_OFF);         // [128]

        int b = blockIdx.x;
        int q  = tid >> 8;         // k-half
        int i2 = tid & 255;        // row-pair index
        int r0 = 2 * i2, r1 = r0 + 1;
        int kb = 64 * q;

        const float* w0base = Whh + (long)r0 * H_ + kb;
        const float* w1base = Whh + (long)r1 * H_ + kb;
        unsigned long long w0[32], w1[16];
        #pragma unroll
        for (int k2 = 0; k2 < 32; k2++) w0[k2] = ((const unsigned long long*)w0base)[k2];
        #pragma unroll
        for (int k2 = 0; k2 < 16; k2++) w1[k2] = ((const unsigned long long*)w1base)[k2];
        #pragma unroll
        for (int kp = 0; kp < 16; kp++)
            wsm2[(q * 16 + kp) * 256 + i2] = ((const float2*)(w1base + 32))[kp];

        float c = 0.f;
        if (tid < H_) h_sm[tid] = 0.f;
        __syncthreads();

        const float* xp = g_xpre + (long)b * L_ * G4H_ + r0;
        float2 xr = make_float2(0.f, 0.f);

        for (int t = 0; t < L_; t++) {
            // chunk gate: wait for xpre chunk, then load this step's x fresh
            if ((t & (CHUNK - 1)) == 0) {
                if (tid == 0) {
                    const int* flag = &g_xdone[b * NCHUNK + (t >> 7)];
                    while (ld_acquire(flag) == 0) __nanosleep(100);
                }
                __syncthreads();
                if (q == 0) xr = *(const float2*)(xp + (long)t * G4H_);
            }
            // prefetch next step's x only within the published chunk
            float2 xnext = make_float2(0.f, 0.f);
            if (q == 0 && ((t + 1) & (CHUNK - 1)) != 0)
                xnext = *(const float2*)(xp + (long)(t + 1) * G4H_);

            unsigned long long acc0 = pack2(xr.x, 0.f);
            unsigned long long acc1 = pack2(xr.y, 0.f);
            const ulonglong2* h2 = (const ulonglong2*)(h_sm + kb);

            #pragma unroll
            for (int k4 = 0; k4 < 8; k4++) {
                ulonglong2 hv = h2[k4];
                acc0 = ffma2(hv.x, w0[2 * k4], acc0);
                acc0 = ffma2(hv.y, w0[2 * k4 + 1], acc0);
                acc1 = ffma2(hv.x, w1[2 * k4], acc1);
                acc1 = ffma2(hv.y, w1[2 * k4 + 1], acc1);
            }
            #pragma unroll
            for (int k4 = 8; k4 < 16; k4++) {
                ulonglong2 hv = h2[k4];
                int kp = 2 * (k4 - 8);
                float2 wa = wsm2[(q * 16 + kp) * 256 + i2];
                float2 wb = wsm2[(q * 16 + kp + 1) * 256 + i2];
                acc0 = ffma2(hv.x, w0[2 * k4], acc0);
                acc0 = ffma2(hv.y, w0[2 * k4 + 1], acc0);
                acc1 = ffma2(hv.x, pack2(wa.x, wa.y), acc1);
                acc1 = ffma2(hv.y, pack2(wb.x, wb.y), acc1);
            }
            float2 a0 = unpack2(acc0), a1 = unpack2(acc1);
            *(float2*)&psum[q * G4H_ + r0] = make_float2(a0.x + a0.y, a1.x + a1.y);
            __syncthreads();

            if (tid < H_) {
                float gi = psum[tid]            + psum[G4H_ + tid];
                float gf = psum[H_ + tid]       + psum[G4H_ + H_ + tid];
                float gg = psum[2 * H_ + tid]   + psum[G4H_ + 2 * H_ + tid];
                float go = psum[3 * H_ + tid]   + psum[G4H_ + 3 * H_ + tid];
                float si = fast_sigmoid(gi);
                float sf = fast_sigmoid(gf);
                float tg = fast_tanh(gg);
                float so = fast_sigmoid(go);
                c = sf * c + si * tg;
                float h = so * fast_tanh(c);
                h_sm[tid] = h;
                g_hs[((long)b * L_ + t) * H_ + tid] = h;
            }
            __syncthreads();

            // publish completed chunk for pred-GEMM consumers
            if (((t & (CHUNK - 1)) == (CHUNK - 1)) && tid == 0) {
                __threadfence();
                atomicExch(&g_progress[b], t + 1);
            }
            xr = xnext;
        }
    } else {
        // ================= consumers =================
        unsigned* As = (unsigned*)smem_raw;          // [GBUF]
        unsigned* Bs = As + GBUF;                    // [GBUF]
        int cta = blockIdx.x - B_;

        // ---- phase 1: xpre tiles, chunk-major so producers unblock early ----
        for (int idx = cta; idx < NXTILES_TOT; idx += NPRED) {
            int cchunk = idx / (B_ * NXTILE);
            int rem    = idx % (B_ * NXTILE);
            int b      = rem / NXTILE;
            int nt     = rem % NXTILE;

            gemm_tile_k128(g_xcat, Wih, g_bias2, g_xpre,
                           b * L_ + cchunk * CHUNK, nt * 128, G4H_, As, Bs, tid);

            // strict release publish: every thread fences its own stores,
            // barrier orders them before tid0's atomics
            __threadfence();
            __syncthreads();
            if (tid == 0) {
                int slot = b * NCHUNK + cchunk;
                int v = atomicAdd(&g_xcnt[slot], 1);
                if (v == NXTILE - 1) atomicExch(&g_xdone[slot], 1);
            }
        }

        // ---- phase 2: pred tiles gated on recurrence progress ----
        for (int idx = cta; idx < NTILES_TOT; idx += NPRED) {
            int cchunk = idx / (B_ * NTILE);
            int rem    = idx % (B_ * NTILE);
            int b      = rem / NTILE;
            int nt     = rem % NTILE;

            if (tid == 0) {
                int need = (cchunk + 1) * CHUNK;
                while (ld_acquire(&g_progress[b]) < need) __nanosleep(200);
            }
            __syncthreads();

            gemm_tile_k128(g_hs, WpredT, b_pred, out,
                           b * L_ + cchunk * CHUNK, nt * 128, VOCAB_, As, Bs, tid);
        }
    }
}

// ---------------- launch ----------------------------------------------------
extern "C" void kernel_launch(void* const* d_in, const int* in_sizes, int n_in,
                              void* d_out, int out_size) {
    const float* dec_hidden = (const float*)d_in[0];
    const int*   ids        = (const int*)d_in[1];
    const int*   lens       = (const int*)d_in[2];
    const float* char_emb   = (const float*)d_in[3];
    const float* W_proj     = (const float*)d_in[4];
    const float* b_proj     = (const float*)d_in[5];
    const float* W_ih       = (const float*)d_in[6];
    const float* W_hh       = (const float*)d_in[7];
    const float* b_ih       = (const float*)d_in[8];
    const float* b_hh       = (const float*)d_in[9];
    const float* W_pred     = (const float*)d_in[10];
    const float* b_pred     = (const float*)d_in[11];
    float* out = (float*)d_out;

    float *p_rep, *p_WprojT, *p_WpredT;
    cudaGetSymbolAddress((void**)&p_rep,    g_rep);
    cudaGetSymbolAddress((void**)&p_WprojT, g_WprojT);
    cudaGetSymbolAddress((void**)&p_WpredT, g_WpredT);

    // 0) prep: combine biases + reset sync state; transpose W_proj, W_pred
    prep_bias_kernel<<<(G4H_ + 255) / 256, 256>>>(b_ih, b_hh);
    transpose_kernel<<<dim3(G4H_ / 32, DIM_ / 32), dim3(32, 8)>>>(W_proj, p_WprojT, DIM_, G4H_);
    transpose_kernel<<<dim3(VOCAB_ / 32, H_ / 32), dim3(32, 8)>>>(W_pred, p_WpredT, H_, VOCAB_);

    // 1) word-length prefix sums
    scan_lens_kernel<<<B_, N_>>>(lens);

    // 2) proj GEMM: rep = dec_hidden @ W_proj + b_proj   [8192,768]x[768,512]
    tf32_gemm_kernel<<<dim3(G4H_ / 128, (B_ * N_) / 128), 256>>>(
        B_ * N_, G4H_, DIM_, dec_hidden, p_WprojT, b_proj, p_rep);

    // 3) build x_cat: char half + zero padded half, then ragged scatter
    build_char_kernel<<<(B_ * L_ * 32) / 256, 256>>>(ids, char_emb);
    scatter_pad_kernel<<<(B_ * N_ * 32) / 256, 256>>>(lens);

    // 4+5+6) fused: xpre GEMM (consumers, phase 1) + recurrence (16 producers)
    //        + pred GEMM (consumers, phase 2)
    cudaFuncSetAttribute(fused_rec_pred_kernel,
                         cudaFuncAttributeMaxDynamicSharedMemorySize, LSTM_SMEM);
    fused_rec_pred_kernel<<<B_ + NPRED, 512, LSTM_SMEM>>>(W_hh, W_ih, p_WpredT, b_pred, out);
}